// round 5
// baseline (speedup 1.0000x reference)
#include <cuda_runtime.h>
#include <cuda_bf16.h>
#include <cstdint>

#define BSZ 128
#define DIM 1024
#define NCLS 32768
#define INV_TAU 20.0f
#define THRESH 20.0f
#define NBLK (NCLS / 128)   // 256 gemm blocks

// Scratch (device globals: no allocations allowed)
__device__ alignas(16) __nv_bfloat16 g_abf[BSZ * DIM];  // bf16 inputs
__device__ alignas(16) float g_pse[BSZ * NBLK];         // partial sumexp(s-20)
__device__ alignas(16) float g_pcn[BSZ * NBLK];         // partial count > 20
__device__ alignas(16) float g_pss[BSZ * NBLK];         // partial sum of s > 20
__device__ alignas(16) float g_st[BSZ];                 // s[target[b]]

__device__ __forceinline__ unsigned su32(const void* p) {
    return (unsigned)__cvta_generic_to_shared(p);
}

__device__ __forceinline__ void mma_bf16(float* c, const uint32_t* a, const uint32_t* b) {
    asm volatile(
        "mma.sync.aligned.m16n8k16.row.col.f32.bf16.bf16.f32 "
        "{%0,%1,%2,%3}, {%4,%5,%6,%7}, {%8,%9}, {%0,%1,%2,%3};\n"
        : "+f"(c[0]), "+f"(c[1]), "+f"(c[2]), "+f"(c[3])
        : "r"(a[0]), "r"(a[1]), "r"(a[2]), "r"(a[3]), "r"(b[0]), "r"(b[1]));
}

__device__ __forceinline__ uint32_t pack_bf16x2(float lo, float hi) {
    return ((uint32_t)__bfloat16_as_ushort(__float2bfloat16(hi)) << 16) |
           (uint32_t)__bfloat16_as_ushort(__float2bfloat16(lo));
}

// ---------------------------------------------------------------------------
// K0: convert inputs to bf16 once
// ---------------------------------------------------------------------------
__global__ void convert_inputs_kernel(const float* __restrict__ in) {
    int i = blockIdx.x * blockDim.x + threadIdx.x;
    if (i < BSZ * DIM) g_abf[i] = __float2bfloat16(in[i]);
}

// ---------------------------------------------------------------------------
// K1: GEMM (scores = inputs @ em^T * 20) fused with em -> out_em copy and
// per-tile softmax statistics. Double-buffered smem, ONE barrier per K-iter.
// ---------------------------------------------------------------------------
#define BM 128
#define BN 128
#define BK 32
#define PADK 40   // 80B row stride: conflict-light ldmatrix/STS

__global__ __launch_bounds__(256, 2) void gemm_fused_kernel(const float* __restrict__ em,
                                                            float* __restrict__ out_em,
                                                            const int* __restrict__ targets) {
    __shared__ __nv_bfloat16 sA[2][BM * PADK];
    __shared__ __nv_bfloat16 sB[2][BN * PADK];
    __shared__ float sRed[3][BSZ][4];
    __shared__ int sT[BSZ];

    const int tid = threadIdx.x;
    const int warp = tid >> 5;
    const int lane = tid & 31;
    const int warpM = warp >> 2;  // 0..1
    const int warpN = warp & 3;   // 0..3
    const int cBase = blockIdx.x * BN;

    if (tid < BSZ) sT[tid] = targets[tid];

    float acc[4][4][4];
#pragma unroll
    for (int i = 0; i < 4; i++)
#pragma unroll
        for (int j = 0; j < 4; j++)
#pragma unroll
            for (int k = 0; k < 4; k++) acc[i][j][k] = 0.0f;

    // A chunks: row=tid>>2 (+64), 8-bf16 col chunk ck=(tid&3)*8
    const int aRow0 = tid >> 2, aCk0 = (tid & 3) * 8;
    const int aRow1 = aRow0 + 64;
    // B chunks: c = tid + it*256 in [0,1024): row=c>>3, col4=(c&7)*4 (floats)

    uint4 ra[2];
    float4 rbv[4];

#define LOAD_TILE(K0)                                                                   \
    do {                                                                                \
        ra[0] = *reinterpret_cast<const uint4*>(&g_abf[aRow0 * DIM + (K0) + aCk0]);     \
        ra[1] = *reinterpret_cast<const uint4*>(&g_abf[aRow1 * DIM + (K0) + aCk0]);     \
        _Pragma("unroll") for (int it = 0; it < 4; it++) {                              \
            int c = tid + it * 256;                                                     \
            int row = c >> 3, col4 = (c & 7) * 4;                                       \
            rbv[it] = *reinterpret_cast<const float4*>(                                 \
                &em[(size_t)(cBase + row) * DIM + (K0) + col4]);                        \
        }                                                                               \
    } while (0)

#define STAGE_TILE(BUF, K0)                                                             \
    do {                                                                                \
        *reinterpret_cast<uint4*>(&sA[BUF][aRow0 * PADK + aCk0]) = ra[0];               \
        *reinterpret_cast<uint4*>(&sA[BUF][aRow1 * PADK + aCk0]) = ra[1];               \
        _Pragma("unroll") for (int it = 0; it < 4; it++) {                              \
            int c = tid + it * 256;                                                     \
            int row = c >> 3, col4 = (c & 7) * 4;                                       \
            size_t base = (size_t)(cBase + row) * DIM + (K0) + col4;                    \
            float4 v = rbv[it];                                                         \
            out_em[base + 0] = v.x;                                                     \
            out_em[base + 1] = v.y;                                                     \
            out_em[base + 2] = v.z;                                                     \
            out_em[base + 3] = v.w;                                                     \
            *reinterpret_cast<uint2*>(&sB[BUF][row * PADK + col4]) =                    \
                make_uint2(pack_bf16x2(v.x, v.y), pack_bf16x2(v.z, v.w));               \
        }                                                                               \
    } while (0)

    LOAD_TILE(0);
    STAGE_TILE(0, 0);
    __syncthreads();

    const int NT = DIM / BK;  // 32
    for (int kt = 0; kt < NT; kt++) {
        const int cur = kt & 1;
        const bool more = (kt + 1 < NT);
        if (more) LOAD_TILE((kt + 1) * BK);

        // ---- MMA on buf[cur], hides next-tile LDGs ----
#pragma unroll
        for (int ks = 0; ks < BK; ks += 16) {
            uint32_t afr[4][4];
            {
                int r = lane & 15;
                int c8 = (lane >> 4) * 8;
#pragma unroll
                for (int i = 0; i < 4; i++) {
                    unsigned addr = su32(&sA[cur][(warpM * 64 + i * 16 + r) * PADK + ks + c8]);
                    asm volatile(
                        "ldmatrix.sync.aligned.m8n8.x4.shared.b16 {%0,%1,%2,%3}, [%4];"
                        : "=r"(afr[i][0]), "=r"(afr[i][1]), "=r"(afr[i][2]), "=r"(afr[i][3])
                        : "r"(addr));
                }
            }
            uint32_t bfr[4][2];
            {
                int rb8 = lane & 7;
                int cb8 = ((lane >> 3) & 1) * 8;
#pragma unroll
                for (int j = 0; j < 4; j++) {
                    unsigned addr = su32(&sB[cur][(warpN * 32 + j * 8 + rb8) * PADK + ks + cb8]);
                    asm volatile(
                        "ldmatrix.sync.aligned.m8n8.x2.shared.b16 {%0,%1}, [%2];"
                        : "=r"(bfr[j][0]), "=r"(bfr[j][1])
                        : "r"(addr));
                }
            }
#pragma unroll
            for (int i = 0; i < 4; i++)
#pragma unroll
                for (int j = 0; j < 4; j++) mma_bf16(acc[i][j], afr[i], bfr[j]);
        }

        if (more) STAGE_TILE(cur ^ 1, (kt + 1) * BK);
        __syncthreads();
    }

    // ---- fused epilogue: per-row partial statistics ----
    const int r = lane >> 2;
#pragma unroll
    for (int i = 0; i < 4; i++) {
#pragma unroll
        for (int half = 0; half < 2; half++) {
            int bb = warpM * 64 + i * 16 + r + half * 8;   // global sample index
            int tgt = sT[bb];
            float se = 0.0f, cn = 0.0f, ss = 0.0f;
#pragma unroll
            for (int j = 0; j < 4; j++) {
                int cc = cBase + warpN * 32 + j * 8 + (lane & 3) * 2;
                float v0 = acc[i][j][half * 2 + 0] * INV_TAU;
                float v1 = acc[i][j][half * 2 + 1] * INV_TAU;
                se += __expf(v0 - 20.0f) + __expf(v1 - 20.0f);
                if (v0 > THRESH) { cn += 1.0f; ss += v0; }
                if (v1 > THRESH) { cn += 1.0f; ss += v1; }
                if (cc == tgt) g_st[bb] = v0;
                if (cc + 1 == tgt) g_st[bb] = v1;
            }
#pragma unroll
            for (int o = 1; o < 4; o <<= 1) {
                se += __shfl_xor_sync(~0u, se, o);
                cn += __shfl_xor_sync(~0u, cn, o);
                ss += __shfl_xor_sync(~0u, ss, o);
            }
            if ((lane & 3) == 0) {
                sRed[0][bb][warpN] = se;
                sRed[1][bb][warpN] = cn;
                sRed[2][bb][warpN] = ss;
            }
        }
    }
    __syncthreads();
    if (tid < BSZ) {
        float se = sRed[0][tid][0] + sRed[0][tid][1] + sRed[0][tid][2] + sRed[0][tid][3];
        float cn = sRed[1][tid][0] + sRed[1][tid][1] + sRed[1][tid][2] + sRed[1][tid][3];
        float ss = sRed[2][tid][0] + sRed[2][tid][1] + sRed[2][tid][2] + sRed[2][tid][3];
        g_pse[tid * NBLK + blockIdx.x] = se;
        g_pcn[tid * NBLK + blockIdx.x] = cn;
        g_pss[tid * NBLK + blockIdx.x] = ss;
    }
}

// ---------------------------------------------------------------------------
// K2: fused scatter + loss.
// Blocks 0..127: EMA scatter chains (O(1) head detection via smem + ballot).
// Block 128: reduce partials for all samples (warp per sample batch), write
// ks and the final loss mean.
// ---------------------------------------------------------------------------
__global__ __launch_bounds__(256) void scatter_loss_kernel(const float* __restrict__ inputs,
                                                           const int* __restrict__ targets,
                                                           const int* __restrict__ epoch,
                                                           float* __restrict__ out_em,
                                                           float* __restrict__ out) {
    const int t = threadIdx.x;
    const int warp = t >> 5;
    const int lane = t & 31;

    if (blockIdx.x == BSZ) {
        // ---- loss block ----
        __shared__ float sLoss[BSZ];
        for (int b = warp; b < BSZ; b += 8) {
            float se = 0.0f, cn = 0.0f, ss = 0.0f;
#pragma unroll
            for (int i = lane; i < NBLK; i += 32) {
                se += g_pse[b * NBLK + i];
                cn += g_pcn[b * NBLK + i];
                ss += g_pss[b * NBLK + i];
            }
#pragma unroll
            for (int o = 16; o; o >>= 1) {
                se += __shfl_xor_sync(~0u, se, o);
                cn += __shfl_xor_sync(~0u, cn, o);
                ss += __shfl_xor_sync(~0u, ss, o);
            }
            if (lane == 0) {
                float st = g_st[b];
                float lse = 20.0f + logf(se);
                float logpt = st - lse;
                int n = (int)(cn + 0.5f);
                float loss;
                if (n > 1) {
                    float kk = 1.0f / ((float)n * logf((float)n));
                    int ta = (st > THRESH) ? 1 : 0;
                    float extra = kk * ((ss - (ta ? st : 0.0f)) - (float)(n - ta) * lse);
                    loss = -(extra + logpt);
                } else {
                    loss = -logpt;
                }
                sLoss[b] = loss;
                out[1 + b] = cn;  // ks
            }
        }
        __syncthreads();
        if (t == 0) {
            float acc = 0.0f;
            for (int i = 0; i < BSZ; i++) acc += sLoss[i];
            out[0] = acc / (float)BSZ;
        }
        return;
    }

    // ---- scatter block ----
    __shared__ int sT[BSZ];
    __shared__ float red[8];
    __shared__ float bc;
    if (t < BSZ) sT[t] = targets[t];
    __syncthreads();

    const int b = blockIdx.x;
    const int y = sT[b];
    int match = (t < b && sT[t] == y) ? 1 : 0;
    if (__syncthreads_or(match)) return;  // not the chain head (uniform)

    const float mu = fminf(0.4f / 60.0f * (float)(epoch[0] + 1), 1.0f);
    const float omu = 1.0f - mu;

    // each thread owns 4 consecutive elements of the row
    const size_t rbase = (size_t)y * DIM + t * 4;
    float row[4];
#pragma unroll
    for (int q = 0; q < 4; q++) row[q] = out_em[rbase + q];  // scalar: base 4 mod 16

    for (int j = b; j < BSZ; j++) {
        if (sT[j] != y) continue;  // uniform across block (smem)
        float4 x = *reinterpret_cast<const float4*>(&inputs[(size_t)j * DIM + t * 4]);
        float v0 = mu * row[0] + omu * x.x;
        float v1 = mu * row[1] + omu * x.y;
        float v2 = mu * row[2] + omu * x.z;
        float v3 = mu * row[3] + omu * x.w;
        float sq = v0 * v0 + v1 * v1 + v2 * v2 + v3 * v3;
#pragma unroll
        for (int o = 16; o; o >>= 1) sq += __shfl_xor_sync(~0u, sq, o);
        if (lane == 0) red[warp] = sq;
        __syncthreads();
        if (t == 0) {
            float s = 0.0f;
#pragma unroll
            for (int i = 0; i < 8; i++) s += red[i];
            bc = s;
        }
        __syncthreads();
        float rn = rsqrtf(bc);
        row[0] = v0 * rn; row[1] = v1 * rn; row[2] = v2 * rn; row[3] = v3 * rn;
    }
#pragma unroll
    for (int q = 0; q < 4; q++) out_em[rbase + q] = row[q];
}

// ---------------------------------------------------------------------------
// Entry point. Output layout (float32): [loss(1), ks(128), new_em(32768*1024)]
// ---------------------------------------------------------------------------
extern "C" void kernel_launch(void* const* d_in, const int* in_sizes, int n_in,
                              void* d_out, int out_size) {
    const float* inputs = (const float*)d_in[0];
    const float* em = (const float*)d_in[1];
    const int* targets = (const int*)d_in[2];
    const int* epoch = (const int*)d_in[3];
    float* out = (float*)d_out;
    float* out_em = out + 1 + BSZ;

    convert_inputs_kernel<<<512, 256>>>(inputs);
    gemm_fused_kernel<<<NBLK, 256>>>(em, out_em, targets);
    scatter_loss_kernel<<<BSZ + 1, 256>>>(inputs, targets, epoch, out_em, out);
}